// round 7
// baseline (speedup 1.0000x reference)
#include <cuda_runtime.h>
#include <cuda_fp16.h>
#include <math.h>

#define NB   4
#define FSZ  65536            // F*S
#define CFS  4194304          // C*F*S
#define PW   68               // half2 words per kw-row in sB
#define PU   72               // halves per px-row in sU (9 uint4)
#define PX   72               // floats per ch-row in sX/sY
#define EPSV 1e-5

// ---------------- scratch (no allocs allowed) ----------------
__device__ double g_acc[16];                          // per batch: {sx,sxx,sy,syy}
__device__ float  g_p[NB * 64];                       // post-GLU channel sums
__device__ __align__(16) __half g_u[(size_t)NB * CFS];// post-GLU activations, [b][px][ch]

// ---------------- helpers ----------------
__device__ __forceinline__ float sigm(float v) { return 1.f / (1.f + __expf(-v)); }
__device__ __forceinline__ unsigned packh2(float a, float b) {
    __half2 h = __floats2half2_rn(a, b);   // low = a, high = b
    return *(unsigned*)&h;
}
__device__ __forceinline__ void mma16(float acc[4], const unsigned a[4],
                                      unsigned b0, unsigned b1) {
    asm volatile(
        "mma.sync.aligned.m16n8k16.row.col.f32.f16.f16.f32 "
        "{%0,%1,%2,%3},{%4,%5,%6,%7},{%8,%9},{%0,%1,%2,%3};\n"
        : "+f"(acc[0]), "+f"(acc[1]), "+f"(acc[2]), "+f"(acc[3])
        : "r"(a[0]), "r"(a[1]), "r"(a[2]), "r"(a[3]), "r"(b0), "r"(b1));
}
// A fragment for W rows chA (mma rows 0-7 via lane/4) and chB (rows 8-15); t = lane&3
__device__ __forceinline__ void load_wfrag(unsigned A[4][4], const float* __restrict__ W,
                                           int chA, int chB, int t) {
#pragma unroll
    for (int kt = 0; kt < 4; ++kt) {
        int k0 = kt * 16 + 2 * t;
        A[kt][0] = packh2(W[chA * 64 + k0],     W[chA * 64 + k0 + 1]);
        A[kt][1] = packh2(W[chB * 64 + k0],     W[chB * 64 + k0 + 1]);
        A[kt][2] = packh2(W[chA * 64 + k0 + 8], W[chA * 64 + k0 + 9]);
        A[kt][3] = packh2(W[chB * 64 + k0 + 8], W[chB * 64 + k0 + 9]);
    }
}

// ---------------- K0: zero accumulators ----------------
__global__ void k_zero() {
    int tid = threadIdx.x;
    if (tid < 16) g_acc[tid] = 0.0;
    g_p[tid] = 0.f;
}

// ---------------- K1: LN1 stats ----------------
__global__ __launch_bounds__(256) void k_stats1(const float* __restrict__ x) {
    int bat = blockIdx.x >> 9;
    int chunk = blockIdx.x & 511;
    size_t base = (size_t)bat * CFS + (size_t)chunk * 8192;
    float s = 0.f, ss = 0.f;
#pragma unroll
    for (int it = 0; it < 8; ++it) {
        float4 v = *(const float4*)(x + base + (size_t)(threadIdx.x + 256 * it) * 4);
        s  += (v.x + v.y) + (v.z + v.w);
        ss += (v.x * v.x + v.y * v.y) + (v.z * v.z + v.w * v.w);
    }
#pragma unroll
    for (int o = 16; o; o >>= 1) {
        s  += __shfl_xor_sync(0xffffffffu, s,  o);
        ss += __shfl_xor_sync(0xffffffffu, ss, o);
    }
    __shared__ float red[16];
    int w = threadIdx.x >> 5, lane = threadIdx.x & 31;
    if (!lane) { red[w] = s; red[8 + w] = ss; }
    __syncthreads();
    if (threadIdx.x == 0) {
        float S = 0.f, SS = 0.f;
#pragma unroll
        for (int i = 0; i < 8; ++i) { S += red[i]; SS += red[8 + i]; }
        atomicAdd(&g_acc[bat * 4 + 0], (double)S);
        atomicAdd(&g_acc[bat * 4 + 1], (double)SS);
    }
}

// ---------------- K2: LN1 -> GEMM1(f16) -> dw affine -> GLU -> u(half), p ----------------
__global__ __launch_bounds__(256) void k_br1(
    const float* __restrict__ x,   const float* __restrict__ lnw,
    const float* __restrict__ lnb, const float* __restrict__ W1,
    const float* __restrict__ b1,  const float* __restrict__ dww,
    const float* __restrict__ dwb) {
    __shared__ unsigned sB[32 * PW];   // [kw][px] half2 pairs of LN output
    __shared__ __half  sU[64 * PU];    // [px][ch] u staging
    __shared__ float st[2];
    int tid = threadIdx.x, w = tid >> 5, lane = tid & 31, g = lane >> 2, t = lane & 3;
    int bat = blockIdx.x >> 10, tile = blockIdx.x & 1023;
    size_t base  = (size_t)bat * CFS + (size_t)tile * 64;
    size_t pbase = (size_t)tile * 64;                       // LN params: no batch dim
    if (tid == 0) {
        double m = g_acc[bat * 4 + 0] / (double)CFS;
        double v = g_acc[bat * 4 + 1] / (double)CFS - m * m;
        st[0] = (float)m;
        st[1] = (float)(1.0 / sqrt(v + EPSV));
    }
    __syncthreads();
    float m1 = st[0], r1 = st[1];
    {   // stage LN1 output as half2 K-pairs: thread owns pixel px, 8 kw rows
        int px = tid & 63, kwg = tid >> 6;
#pragma unroll
        for (int i = 0; i < 8; ++i) {
            int kw = kwg * 8 + i;
            int c0 = 2 * kw, c1 = c0 + 1;
            size_t g0 = base  + (size_t)c0 * FSZ + px;
            size_t g1 = base  + (size_t)c1 * FSZ + px;
            size_t p0 = pbase + (size_t)c0 * FSZ + px;
            size_t p1 = pbase + (size_t)c1 * FSZ + px;
            float l0 = fmaf((x[g0] - m1) * r1, lnw[p0], lnb[p0]);
            float l1 = fmaf((x[g1] - m1) * r1, lnw[p1], lnb[p1]);
            sB[kw * PW + px] = packh2(l0, l1);
        }
    }
    __syncthreads();
    // GEMM1: warp w -> a-channels chA=8w+g (rows 0-7), gate chB=chA+64 (rows 8-15)
    int chA = 8 * w + g, chB = chA + 64;
    unsigned A[4][4];
    load_wfrag(A, W1, chA, chB, t);
    float acc[8][4];
#pragma unroll
    for (int i = 0; i < 8; ++i)
#pragma unroll
        for (int j = 0; j < 4; ++j) acc[i][j] = 0.f;
#pragma unroll
    for (int nt = 0; nt < 8; ++nt) {
        int n0 = nt * 8 + g;
#pragma unroll
        for (int kt = 0; kt < 4; ++kt) {
            unsigned bb0 = sB[(8 * kt + t)     * PW + n0];
            unsigned bb1 = sB[(8 * kt + t + 4) * PW + n0];
            mma16(acc[nt], A[kt], bb0, bb1);
        }
    }
    // epilogue: +b1, dw affine, GLU (a/g pair in-register), u -> sU, p accumulate
    float ba = b1[chA], bg = b1[chB];
    float dwa = dww[chA], dba = dwb[chA], dwg = dww[chB], dbg = dwb[chB];
    float psum = 0.f;
#pragma unroll
    for (int nt = 0; nt < 8; ++nt) {
        int c0 = nt * 8 + 2 * t;
        float a0 = fmaf(acc[nt][0] + ba, dwa, dba);
        float a1 = fmaf(acc[nt][1] + ba, dwa, dba);
        float g0 = fmaf(acc[nt][2] + bg, dwg, dbg);
        float g1 = fmaf(acc[nt][3] + bg, dwg, dbg);
        float u0 = a0 * sigm(g0);
        float u1 = a1 * sigm(g1);
        psum += u0 + u1;
        sU[c0       * PU + chA] = __float2half_rn(u0);
        sU[(c0 + 1) * PU + chA] = __float2half_rn(u1);
    }
    psum += __shfl_xor_sync(0xffffffffu, psum, 1);
    psum += __shfl_xor_sync(0xffffffffu, psum, 2);
    if (t == 0) atomicAdd(&g_p[bat * 64 + chA], psum);
    __syncthreads();
    {   // coalesced write to g_u: tile is a contiguous 8KB block in [px][ch] layout
        uint4* gu = (uint4*)g_u;
        size_t bu = ((size_t)bat * FSZ + (size_t)tile * 64) * 8;  // uint4 units
#pragma unroll
        for (int i = 0; i < 2; ++i) {
            int idx = tid + 256 * i;
            int px = idx >> 3, kq = idx & 7;
            gu[bu + idx] = *(const uint4*)(sU + px * PU + kq * 8);
        }
    }
}

// ---------------- K3: SE gate (coalesced, warp-coop) + y = W2@(u*s)+b2+x ; LN2 stats ----------------
__global__ __launch_bounds__(256) void k_y(
    const float* __restrict__ x,   const float* __restrict__ W2,
    const float* __restrict__ b2,
    const float* __restrict__ aw1, const float* __restrict__ ab1,
    const float* __restrict__ aw2, const float* __restrict__ ab2,
    float* __restrict__ yo) {
    __shared__ unsigned sB[32 * PW];
    __shared__ float sX[64 * PX];
    __shared__ float ssg[64], sp[64], sh[64], red[16];
    int tid = threadIdx.x, w = tid >> 5, lane = tid & 31, g = lane >> 2, t = lane & 3;
    int bat = blockIdx.x >> 10, tile = blockIdx.x & 1023;
    size_t base = (size_t)bat * CFS + (size_t)tile * 64;
    // ---- SE gate, warp-cooperative: 4-lane group (w, g) owns channel c = 8w+g ----
    if (tid < 64) sp[tid] = g_p[bat * 64 + tid] * (1.f / 65536.f);
    __syncthreads();
    {
        int c = 8 * w + g;                 // 0..63, each exactly once
        const float4* a1 = (const float4*)(aw1 + c * 64 + t * 16);
        float part = 0.f;
#pragma unroll
        for (int q = 0; q < 4; ++q) {      // lane covers 16 contiguous k
            float4 wv = a1[q];
            int j = t * 16 + q * 4;
            part += wv.x * sp[j] + wv.y * sp[j + 1] + wv.z * sp[j + 2] + wv.w * sp[j + 3];
        }
        part += __shfl_xor_sync(0xffffffffu, part, 1);
        part += __shfl_xor_sync(0xffffffffu, part, 2);
        if (t == 0) sh[c] = fmaxf(part + ab1[c], 0.f);
        __syncthreads();
        const float4* a2 = (const float4*)(aw2 + c * 64 + t * 16);
        part = 0.f;
#pragma unroll
        for (int q = 0; q < 4; ++q) {
            float4 wv = a2[q];
            int j = t * 16 + q * 4;
            part += wv.x * sh[j] + wv.y * sh[j + 1] + wv.z * sh[j + 2] + wv.w * sh[j + 3];
        }
        part += __shfl_xor_sync(0xffffffffu, part, 1);
        part += __shfl_xor_sync(0xffffffffu, part, 2);
        if (t == 0) ssg[c] = sigm(part + ab2[c]);
    }
    __syncthreads();
    {   // stage u*s (half2 K-pairs) and x (fp32 residual tile)
        const uint4* gu = (const uint4*)g_u;
        size_t bu = ((size_t)bat * FSZ + (size_t)tile * 64) * 8;
#pragma unroll
        for (int i = 0; i < 2; ++i) {
            int idx = tid + 256 * i;
            int px = idx >> 3, kq = idx & 7;
            uint4 v = gu[bu + idx];
            unsigned vv[4] = {v.x, v.y, v.z, v.w};
#pragma unroll
            for (int j = 0; j < 4; ++j) {
                __half2 h = *(__half2*)&vv[j];
                float2 f = __half22float2(h);
                int c = 8 * kq + 2 * j;
                sB[(4 * kq + j) * PW + px] = packh2(f.x * ssg[c], f.y * ssg[c + 1]);
            }
        }
#pragma unroll
        for (int it = 0; it < 4; ++it) {
            int e = (tid + 256 * it) * 4;
            int row = e >> 6, col = e & 63;
            *(float4*)(sX + row * PX + col) = *(const float4*)(x + base + (size_t)row * FSZ + col);
        }
    }
    __syncthreads();
    // GEMM2: 64x64; warp w: m-tile w&3, px half (w>>2)*32
    int mt = w & 3, hf = w >> 2;
    int r0 = mt * 16 + g, r1 = r0 + 8;
    unsigned A[4][4];
    load_wfrag(A, W2, r0, r1, t);
    float acc[4][4];
#pragma unroll
    for (int i = 0; i < 4; ++i)
#pragma unroll
        for (int j = 0; j < 4; ++j) acc[i][j] = 0.f;
#pragma unroll
    for (int nt = 0; nt < 4; ++nt) {
        int n0 = hf * 32 + nt * 8 + g;
#pragma unroll
        for (int kt = 0; kt < 4; ++kt) {
            unsigned bb0 = sB[(8 * kt + t)     * PW + n0];
            unsigned bb1 = sB[(8 * kt + t + 4) * PW + n0];
            mma16(acc[nt], A[kt], bb0, bb1);
        }
    }
    float bc0 = b2[r0], bc1 = b2[r1];
    float sy = 0.f, syy = 0.f;
#pragma unroll
    for (int nt = 0; nt < 4; ++nt) {
        int c0 = hf * 32 + nt * 8 + 2 * t;
        float y00 = acc[nt][0] + bc0 + sX[r0 * PX + c0];
        float y01 = acc[nt][1] + bc0 + sX[r0 * PX + c0 + 1];
        float y10 = acc[nt][2] + bc1 + sX[r1 * PX + c0];
        float y11 = acc[nt][3] + bc1 + sX[r1 * PX + c0 + 1];
        sX[r0 * PX + c0]     = y00;   // in-place (element owned by this thread)
        sX[r0 * PX + c0 + 1] = y01;
        sX[r1 * PX + c0]     = y10;
        sX[r1 * PX + c0 + 1] = y11;
        sy  += (y00 + y01) + (y10 + y11);
        syy += (y00 * y00 + y01 * y01) + (y10 * y10 + y11 * y11);
    }
#pragma unroll
    for (int o = 16; o; o >>= 1) {
        sy  += __shfl_xor_sync(0xffffffffu, sy,  o);
        syy += __shfl_xor_sync(0xffffffffu, syy, o);
    }
    if (!lane) { red[w] = sy; red[8 + w] = syy; }
    __syncthreads();
    if (tid == 0) {
        float S = 0.f, SS = 0.f;
#pragma unroll
        for (int i = 0; i < 8; ++i) { S += red[i]; SS += red[8 + i]; }
        atomicAdd(&g_acc[bat * 4 + 2], (double)S);
        atomicAdd(&g_acc[bat * 4 + 3], (double)SS);
    }
#pragma unroll
    for (int it = 0; it < 4; ++it) {
        int e = (tid + 256 * it) * 4;
        int row = e >> 6, col = e & 63;
        *(float4*)(yo + base + (size_t)row * FSZ + col) = *(float4*)(sX + row * PX + col);
    }
}

// ---------------- K4: LN2 -> GEMM3(f16) -> GLU -> GEMM4(f16) -> +y ----------------
__global__ __launch_bounds__(256) void k_br2(
    const float* __restrict__ lnw, const float* __restrict__ lnb,
    const float* __restrict__ W3,  const float* __restrict__ b3,
    const float* __restrict__ W4,  const float* __restrict__ b4,
    float* __restrict__ io) {
    __shared__ unsigned sB[32 * PW];   // ln2 half2, later u2
    __shared__ float sY[64 * PX];
    __shared__ float st[2];
    int tid = threadIdx.x, w = tid >> 5, lane = tid & 31, g = lane >> 2, t = lane & 3;
    int bat = blockIdx.x >> 10, tile = blockIdx.x & 1023;
    size_t base  = (size_t)bat * CFS + (size_t)tile * 64;
    size_t pbase = (size_t)tile * 64;                       // LN params: no batch dim
    if (tid == 0) {
        double m = g_acc[bat * 4 + 2] / (double)CFS;
        double v = g_acc[bat * 4 + 3] / (double)CFS - m * m;
        st[0] = (float)m;
        st[1] = (float)(1.0 / sqrt(v + EPSV));
    }
    __syncthreads();
    float m2 = st[0], r2 = st[1];
    {   // stage y (fp32) and LN2 output (half2 pairs)
        int px = tid & 63, kwg = tid >> 6;
#pragma unroll
        for (int i = 0; i < 8; ++i) {
            int kw = kwg * 8 + i;
            int c0 = 2 * kw, c1 = c0 + 1;
            float y0 = io[base + (size_t)c0 * FSZ + px];
            float y1 = io[base + (size_t)c1 * FSZ + px];
            sY[c0 * PX + px] = y0;
            sY[c1 * PX + px] = y1;
            size_t p0 = pbase + (size_t)c0 * FSZ + px;
            size_t p1 = pbase + (size_t)c1 * FSZ + px;
            float l0 = fmaf((y0 - m2) * r2, lnw[p0], lnb[p0]);
            float l1 = fmaf((y1 - m2) * r2, lnw[p1], lnb[p1]);
            sB[kw * PW + px] = packh2(l0, l1);
        }
    }
    __syncthreads();
    // GEMM3: 128x64 with GLU row pairing
    int chA = 8 * w + g, chB = chA + 64;
    float acc[8][4];
    {
        unsigned A[4][4];
        load_wfrag(A, W3, chA, chB, t);
#pragma unroll
        for (int i = 0; i < 8; ++i)
#pragma unroll
            for (int j = 0; j < 4; ++j) acc[i][j] = 0.f;
#pragma unroll
        for (int nt = 0; nt < 8; ++nt) {
            int n0 = nt * 8 + g;
#pragma unroll
            for (int kt = 0; kt < 4; ++kt) {
                unsigned bb0 = sB[(8 * kt + t)     * PW + n0];
                unsigned bb1 = sB[(8 * kt + t + 4) * PW + n0];
                mma16(acc[nt], A[kt], bb0, bb1);
            }
        }
    }
    float b3a = b3[chA], b3g = b3[chB];
    __syncthreads();   // all warps done reading ln2 from sB
    {   // GLU -> u2 into sB (half element view): channel chA -> kw=chA>>1, half-slot chA&1
        __half* sBh = (__half*)sB;
        int kw = chA >> 1, hi = chA & 1;
#pragma unroll
        for (int nt = 0; nt < 8; ++nt) {
            int c0 = nt * 8 + 2 * t;
            float u0 = (acc[nt][0] + b3a) * sigm(acc[nt][2] + b3g);
            float u1 = (acc[nt][1] + b3a) * sigm(acc[nt][3] + b3g);
            sBh[((kw * PW + c0)     << 1) + hi] = __float2half_rn(u0);
            sBh[((kw * PW + c0 + 1) << 1) + hi] = __float2half_rn(u1);
        }
    }
    __syncthreads();
    // GEMM4: 64x64 over u2
    int mt = w & 3, hf = w >> 2;
    int r0 = mt * 16 + g, r1 = r0 + 8;
    unsigned A2[4][4];
    load_wfrag(A2, W4, r0, r1, t);
    float ac2[4][4];
#pragma unroll
    for (int i = 0; i < 4; ++i)
#pragma unroll
        for (int j = 0; j < 4; ++j) ac2[i][j] = 0.f;
#pragma unroll
    for (int nt = 0; nt < 4; ++nt) {
        int n0 = hf * 32 + nt * 8 + g;
#pragma unroll
        for (int kt = 0; kt < 4; ++kt) {
            unsigned bb0 = sB[(8 * kt + t)     * PW + n0];
            unsigned bb1 = sB[(8 * kt + t + 4) * PW + n0];
            mma16(ac2[nt], A2[kt], bb0, bb1);
        }
    }
    float b40 = b4[r0], b41 = b4[r1];
#pragma unroll
    for (int nt = 0; nt < 4; ++nt) {
        int c0 = hf * 32 + nt * 8 + 2 * t;
        sY[r0 * PX + c0]     = ac2[nt][0] + b40 + sY[r0 * PX + c0];
        sY[r0 * PX + c0 + 1] = ac2[nt][1] + b40 + sY[r0 * PX + c0 + 1];
        sY[r1 * PX + c0]     = ac2[nt][2] + b41 + sY[r1 * PX + c0];
        sY[r1 * PX + c0 + 1] = ac2[nt][3] + b41 + sY[r1 * PX + c0 + 1];
    }
    __syncthreads();
#pragma unroll
    for (int it = 0; it < 4; ++it) {
        int e = (tid + 256 * it) * 4;
        int row = e >> 6, col = e & 63;
        *(float4*)(io + base + (size_t)row * FSZ + col) = *(float4*)(sY + row * PX + col);
    }
}

// ---------------- launch ----------------
extern "C" void kernel_launch(void* const* d_in, const int* in_sizes, int n_in,
                              void* d_out, int out_size) {
    const float* x   = (const float*)d_in[0];
    const float* l1w = (const float*)d_in[1];
    const float* l1b = (const float*)d_in[2];
    const float* l2w = (const float*)d_in[3];
    const float* l2b = (const float*)d_in[4];
    const float* W1  = (const float*)d_in[5];
    const float* b1  = (const float*)d_in[6];
    const float* dww = (const float*)d_in[7];
    const float* dwb = (const float*)d_in[8];
    const float* aw1 = (const float*)d_in[9];
    const float* ab1 = (const float*)d_in[10];
    const float* aw2 = (const float*)d_in[11];
    const float* ab2 = (const float*)d_in[12];
    const float* W2  = (const float*)d_in[13];
    const float* b2  = (const float*)d_in[14];
    const float* W3  = (const float*)d_in[15];
    const float* b3  = (const float*)d_in[16];
    const float* W4  = (const float*)d_in[17];
    const float* b4  = (const float*)d_in[18];
    float* out = (float*)d_out;

    k_zero  <<<1, 256>>>();
    k_stats1<<<NB * 512, 256>>>(x);
    k_br1   <<<NB * 1024, 256>>>(x, l1w, l1b, W1, b1, dww, dwb);
    k_y     <<<NB * 1024, 256>>>(x, W2, b2, aw1, ab1, aw2, ab2, out);
    k_br2   <<<NB * 1024, 256>>>(l2w, l2b, W3, b3, W4, b4, out);
}

// round 9
// speedup vs baseline: 1.3268x; 1.3268x over previous
#include <cuda_runtime.h>
#include <cuda_fp16.h>
#include <math.h>

#define NB   4
#define NC   64
#define FSZ  65536            // F*S
#define CFS  4194304          // C*F*S
#define TPIX 64               // pixels per tile
#define PAD  72               // smem row stride (72 mod 32 == 8 -> conflict free)
#define EPSV 1e-5

// ---------------- scratch (no allocs allowed) ----------------
__device__ double g_acc[16];                 // per batch: {sx, sxx, sy, syy}
__device__ float  g_p[NB * NC];              // post-GLU channel sums
__device__ __align__(16) __half g_u[(size_t)NB * CFS];  // post-GLU activations, fp16, [b][ch][px]

// ---------------- helpers ----------------
__device__ __forceinline__ unsigned f2tf(float f) {
    unsigned u;
    asm("cvt.rna.tf32.f32 %0, %1;" : "=r"(u) : "f"(f));
    return u;
}
__device__ __forceinline__ void mma8(float acc[4], const unsigned a[4],
                                     unsigned b0, unsigned b1) {
    asm volatile(
        "mma.sync.aligned.m16n8k8.row.col.f32.tf32.tf32.f32 "
        "{%0,%1,%2,%3},{%4,%5,%6,%7},{%8,%9},{%0,%1,%2,%3};\n"
        : "+f"(acc[0]), "+f"(acc[1]), "+f"(acc[2]), "+f"(acc[3])
        : "r"(a[0]), "r"(a[1]), "r"(a[2]), "r"(a[3]), "r"(b0), "r"(b1));
}
__device__ __forceinline__ float sigm(float v) { return 1.f / (1.f + __expf(-v)); }

// ---------------- K0: zero accumulators ----------------
__global__ void k_zero() {
    int t = threadIdx.x;
    if (t < 16) g_acc[t] = 0.0;
    g_p[t] = 0.f;
}

// ---------------- K1: LN1 stats ----------------
__global__ __launch_bounds__(256) void k_stats1(const float* __restrict__ x) {
    int bat = blockIdx.x >> 9;
    int chunk = blockIdx.x & 511;
    size_t base = (size_t)bat * CFS + (size_t)chunk * 8192;
    float s = 0.f, ss = 0.f;
#pragma unroll
    for (int it = 0; it < 8; ++it) {
        float4 v = *(const float4*)(x + base + (size_t)(threadIdx.x + 256 * it) * 4);
        s  += (v.x + v.y) + (v.z + v.w);
        ss += (v.x * v.x + v.y * v.y) + (v.z * v.z + v.w * v.w);
    }
#pragma unroll
    for (int o = 16; o; o >>= 1) {
        s  += __shfl_xor_sync(0xffffffffu, s,  o);
        ss += __shfl_xor_sync(0xffffffffu, ss, o);
    }
    __shared__ float red[16];
    int w = threadIdx.x >> 5, lane = threadIdx.x & 31;
    if (!lane) { red[w] = s; red[8 + w] = ss; }
    __syncthreads();
    if (threadIdx.x == 0) {
        float S = 0.f, SS = 0.f;
#pragma unroll
        for (int i = 0; i < 8; ++i) { S += red[i]; SS += red[8 + i]; }
        atomicAdd(&g_acc[bat * 4 + 0], (double)S);
        atomicAdd(&g_acc[bat * 4 + 1], (double)SS);
    }
}

// ---------------- K2: LN1 -> GEMM1 -> dw affine -> GLU -> u(fp16), accumulate p ----------------
__global__ __launch_bounds__(256) void k_br1(
    const float* __restrict__ x,  const float* __restrict__ lnw,
    const float* __restrict__ lnb, const float* __restrict__ W1,
    const float* __restrict__ pb1, const float* __restrict__ dww,
    const float* __restrict__ dwb) {
    __shared__ float sm[NC * PAD];
    __shared__ float st[2];
    int tid = threadIdx.x, w = tid >> 5, lane = tid & 31;
    int bat = blockIdx.x >> 10;
    int tile = blockIdx.x & 1023;
    size_t base  = (size_t)bat * CFS + (size_t)tile * TPIX;
    size_t pbase = (size_t)tile * TPIX;                      // LN params: NO batch dim
    if (tid == 0) {
        double m = g_acc[bat * 4 + 0] * (1.0 / (double)CFS);
        double v = g_acc[bat * 4 + 1] * (1.0 / (double)CFS) - m * m;
        st[0] = (float)m;
        st[1] = (float)(1.0 / sqrt(v + EPSV));
    }
    __syncthreads();
    float m1 = st[0], r1 = st[1];
#pragma unroll
    for (int it = 0; it < 4; ++it) {
        int e = (tid + 256 * it) * 4;
        int row = e >> 6, col = e & 63;
        size_t g  = base  + (size_t)row * FSZ + col;
        size_t gp = pbase + (size_t)row * FSZ + col;
        float4 xv = *(const float4*)(x + g);
        float4 wv = *(const float4*)(lnw + gp);
        float4 bv = *(const float4*)(lnb + gp);
        float4 o;
        o.x = __uint_as_float(f2tf(fmaf((xv.x - m1) * r1, wv.x, bv.x)));
        o.y = __uint_as_float(f2tf(fmaf((xv.y - m1) * r1, wv.y, bv.y)));
        o.z = __uint_as_float(f2tf(fmaf((xv.z - m1) * r1, wv.z, bv.z)));
        o.w = __uint_as_float(f2tf(fmaf((xv.w - m1) * r1, wv.w, bv.w)));
        *(float4*)(sm + row * PAD + col) = o;
    }
    __syncthreads();
    // A fragments: warp w owns a-channels [8w,8w+8) (rows 0-7) and gate channels +64 (rows 8-15)
    int ra = 8 * w + (lane >> 2), rg = ra + 64, kc = lane & 3;
    unsigned A[8][4];
#pragma unroll
    for (int kt = 0; kt < 8; ++kt) {
        int k0 = kt * 8 + kc;
        A[kt][0] = f2tf(W1[ra * 64 + k0]);
        A[kt][1] = f2tf(W1[rg * 64 + k0]);
        A[kt][2] = f2tf(W1[ra * 64 + k0 + 4]);
        A[kt][3] = f2tf(W1[rg * 64 + k0 + 4]);
    }
    float acc[8][4];
#pragma unroll
    for (int i = 0; i < 8; ++i)
#pragma unroll
        for (int j = 0; j < 4; ++j) acc[i][j] = 0.f;
#pragma unroll
    for (int nt = 0; nt < 8; ++nt) {
        int n0 = nt * 8 + (lane >> 2);
#pragma unroll
        for (int kt = 0; kt < 8; ++kt) {
            int kr = kt * 8 + kc;
            unsigned bb0 = __float_as_uint(sm[kr * PAD + n0]);
            unsigned bb1 = __float_as_uint(sm[(kr + 4) * PAD + n0]);
            mma8(acc[nt], A[kt], bb0, bb1);
        }
    }
    // epilogue: +b1, dw affine, GLU; a/g pair is in-register
    float b1a = pb1[ra], b1g = pb1[rg];
    float dwa = dww[ra], dba = dwb[ra], dwg = dww[rg], dbg = dwb[rg];
    float ur[16];
    float psum = 0.f;
#pragma unroll
    for (int nt = 0; nt < 8; ++nt) {
        float a0 = fmaf(acc[nt][0] + b1a, dwa, dba);
        float a1 = fmaf(acc[nt][1] + b1a, dwa, dba);
        float g0 = fmaf(acc[nt][2] + b1g, dwg, dbg);
        float g1 = fmaf(acc[nt][3] + b1g, dwg, dbg);
        float u0 = a0 * sigm(g0);
        float u1 = a1 * sigm(g1);
        ur[nt * 2] = u0; ur[nt * 2 + 1] = u1;
        psum += u0 + u1;
    }
    psum += __shfl_xor_sync(0xffffffffu, psum, 1);
    psum += __shfl_xor_sync(0xffffffffu, psum, 2);
    if ((lane & 3) == 0) atomicAdd(&g_p[bat * 64 + ra], psum);
    __syncthreads();
#pragma unroll
    for (int nt = 0; nt < 8; ++nt) {
        int c0 = nt * 8 + (lane & 3) * 2;
        sm[ra * PAD + c0]     = ur[nt * 2];
        sm[ra * PAD + c0 + 1] = ur[nt * 2 + 1];
    }
    __syncthreads();
    // write u as fp16, same [ch][px] geometry (uint2 = 4 halves, 2x128B segments per warp)
#pragma unroll
    for (int it = 0; it < 4; ++it) {
        int e = (tid + 256 * it) * 4;
        int row = e >> 6, col = e & 63;
        float4 v = *(float4*)(sm + row * PAD + col);
        __half2 h0 = __floats2half2_rn(v.x, v.y);
        __half2 h1 = __floats2half2_rn(v.z, v.w);
        uint2 o;
        o.x = *(unsigned*)&h0;
        o.y = *(unsigned*)&h1;
        *(uint2*)(g_u + base + (size_t)row * FSZ + col) = o;
    }
}

// ---------------- K3: SE gate (warp-coop, fused) + y = W2@(u*s)+b2+x ; LN2 stats ----------------
__global__ __launch_bounds__(256) void k_y(
    const float* __restrict__ x, const float* __restrict__ W2,
    const float* __restrict__ pb2,
    const float* __restrict__ aw1, const float* __restrict__ ab1,
    const float* __restrict__ aw2, const float* __restrict__ ab2,
    float* __restrict__ yo) {
    __shared__ float smu[NC * PAD];
    __shared__ float smx[NC * PAD];
    __shared__ float ssg[64], sp[64], sh[64];
    __shared__ float red[16];
    int tid = threadIdx.x, w = tid >> 5, lane = tid & 31;
    int bat = blockIdx.x >> 10;
    int tile = blockIdx.x & 1023;
    size_t base = (size_t)bat * CFS + (size_t)tile * TPIX;
    // ---- SE gate, warp-cooperative: 4-lane group (w, lane>>2) owns channel c ----
    if (tid < 64) sp[tid] = g_p[bat * 64 + tid] * (1.f / 65536.f);
    __syncthreads();
    {
        int gq = lane >> 2, t = lane & 3;
        int c = 8 * w + gq;                // 0..63 exactly once
        const float4* a1 = (const float4*)(aw1 + c * 64 + t * 16);
        float part = 0.f;
#pragma unroll
        for (int q = 0; q < 4; ++q) {
            float4 wv = a1[q];
            int j = t * 16 + q * 4;
            part += wv.x * sp[j] + wv.y * sp[j + 1] + wv.z * sp[j + 2] + wv.w * sp[j + 3];
        }
        part += __shfl_xor_sync(0xffffffffu, part, 1);
        part += __shfl_xor_sync(0xffffffffu, part, 2);
        if (t == 0) sh[c] = fmaxf(part + ab1[c], 0.f);
        __syncthreads();
        const float4* a2 = (const float4*)(aw2 + c * 64 + t * 16);
        part = 0.f;
#pragma unroll
        for (int q = 0; q < 4; ++q) {
            float4 wv = a2[q];
            int j = t * 16 + q * 4;
            part += wv.x * sh[j] + wv.y * sh[j + 1] + wv.z * sh[j + 2] + wv.w * sh[j + 3];
        }
        part += __shfl_xor_sync(0xffffffffu, part, 1);
        part += __shfl_xor_sync(0xffffffffu, part, 2);
        if (t == 0) ssg[c] = sigm(part + ab2[c]);
    }
    __syncthreads();
#pragma unroll
    for (int it = 0; it < 4; ++it) {
        int e = (tid + 256 * it) * 4;
        int row = e >> 6, col = e & 63;
        size_t g = base + (size_t)row * FSZ + col;
        uint2 uv = *(const uint2*)(g_u + g);
        float2 f0 = __half22float2(*(__half2*)&uv.x);
        float2 f1 = __half22float2(*(__half2*)&uv.y);
        float4 xv = *(const float4*)(x + g);
        float sg = ssg[row];
        float4 o;
        o.x = __uint_as_float(f2tf(f0.x * sg));
        o.y = __uint_as_float(f2tf(f0.y * sg));
        o.z = __uint_as_float(f2tf(f1.x * sg));
        o.w = __uint_as_float(f2tf(f1.y * sg));
        *(float4*)(smu + row * PAD + col) = o;
        *(float4*)(smx + row * PAD + col) = xv;
    }
    __syncthreads();
    int mt = w & 3, half = w >> 2;
    int r0 = mt * 16 + (lane >> 2), r1r = r0 + 8, kc = lane & 3;
    unsigned A[8][4];
#pragma unroll
    for (int kt = 0; kt < 8; ++kt) {
        int k0 = kt * 8 + kc;
        A[kt][0] = f2tf(W2[r0  * 64 + k0]);
        A[kt][1] = f2tf(W2[r1r * 64 + k0]);
        A[kt][2] = f2tf(W2[r0  * 64 + k0 + 4]);
        A[kt][3] = f2tf(W2[r1r * 64 + k0 + 4]);
    }
    float acc[4][4];
#pragma unroll
    for (int i = 0; i < 4; ++i)
#pragma unroll
        for (int j = 0; j < 4; ++j) acc[i][j] = 0.f;
#pragma unroll
    for (int nt = 0; nt < 4; ++nt) {
        int n0 = half * 32 + nt * 8 + (lane >> 2);
#pragma unroll
        for (int kt = 0; kt < 8; ++kt) {
            int kr = kt * 8 + kc;
            unsigned bb0 = __float_as_uint(smu[kr * PAD + n0]);
            unsigned bb1 = __float_as_uint(smu[(kr + 4) * PAD + n0]);
            mma8(acc[nt], A[kt], bb0, bb1);
        }
    }
    float bc0 = pb2[r0], bc1 = pb2[r1r];
    float yr[16];
    float sy = 0.f, syy = 0.f;
#pragma unroll
    for (int nt = 0; nt < 4; ++nt) {
        int c0 = half * 32 + nt * 8 + (lane & 3) * 2;
        float y00 = acc[nt][0] + bc0 + smx[r0  * PAD + c0];
        float y01 = acc[nt][1] + bc0 + smx[r0  * PAD + c0 + 1];
        float y10 = acc[nt][2] + bc1 + smx[r1r * PAD + c0];
        float y11 = acc[nt][3] + bc1 + smx[r1r * PAD + c0 + 1];
        yr[nt * 4 + 0] = y00; yr[nt * 4 + 1] = y01;
        yr[nt * 4 + 2] = y10; yr[nt * 4 + 3] = y11;
        sy  += (y00 + y01) + (y10 + y11);
        syy += (y00 * y00 + y01 * y01) + (y10 * y10 + y11 * y11);
    }
    __syncthreads();   // all warps done reading smu
#pragma unroll
    for (int nt = 0; nt < 4; ++nt) {
        int c0 = half * 32 + nt * 8 + (lane & 3) * 2;
        smu[r0  * PAD + c0]     = yr[nt * 4 + 0];
        smu[r0  * PAD + c0 + 1] = yr[nt * 4 + 1];
        smu[r1r * PAD + c0]     = yr[nt * 4 + 2];
        smu[r1r * PAD + c0 + 1] = yr[nt * 4 + 3];
    }
#pragma unroll
    for (int o = 16; o; o >>= 1) {
        sy  += __shfl_xor_sync(0xffffffffu, sy,  o);
        syy += __shfl_xor_sync(0xffffffffu, syy, o);
    }
    if (!lane) { red[w] = sy; red[8 + w] = syy; }
    __syncthreads();
    if (tid == 0) {
        float S = 0.f, SS = 0.f;
#pragma unroll
        for (int i = 0; i < 8; ++i) { S += red[i]; SS += red[8 + i]; }
        atomicAdd(&g_acc[bat * 4 + 2], (double)S);
        atomicAdd(&g_acc[bat * 4 + 3], (double)SS);
    }
#pragma unroll
    for (int it = 0; it < 4; ++it) {
        int e = (tid + 256 * it) * 4;
        int row = e >> 6, col = e & 63;
        *(float4*)(yo + base + (size_t)row * FSZ + col) = *(float4*)(smu + row * PAD + col);
    }
}

// ---------------- K4: LN2 -> GEMM3 -> GLU -> GEMM4 -> +y ----------------
__global__ __launch_bounds__(256) void k_br2(
    const float* __restrict__ lnw, const float* __restrict__ lnb,
    const float* __restrict__ W3,  const float* __restrict__ pb3,
    const float* __restrict__ W4,  const float* __restrict__ pb4,
    float* __restrict__ io) {
    __shared__ float smy[NC * PAD];
    __shared__ float smb[NC * PAD];
    __shared__ float st[2];
    int tid = threadIdx.x, w = tid >> 5, lane = tid & 31;
    int bat = blockIdx.x >> 10;
    int tile = blockIdx.x & 1023;
    size_t base  = (size_t)bat * CFS + (size_t)tile * TPIX;
    size_t pbase = (size_t)tile * TPIX;                      // LN params: NO batch dim
    if (tid == 0) {
        double m = g_acc[bat * 4 + 2] * (1.0 / (double)CFS);
        double v = g_acc[bat * 4 + 3] * (1.0 / (double)CFS) - m * m;
        st[0] = (float)m;
        st[1] = (float)(1.0 / sqrt(v + EPSV));
    }
    __syncthreads();
    float m2 = st[0], r2 = st[1];
#pragma unroll
    for (int it = 0; it < 4; ++it) {
        int e = (tid + 256 * it) * 4;
        int row = e >> 6, col = e & 63;
        size_t g  = base  + (size_t)row * FSZ + col;
        size_t gp = pbase + (size_t)row * FSZ + col;
        float4 yv = *(const float4*)(io + g);
        float4 wv = *(const float4*)(lnw + gp);
        float4 bv = *(const float4*)(lnb + gp);
        *(float4*)(smy + row * PAD + col) = yv;
        float4 o;
        o.x = __uint_as_float(f2tf(fmaf((yv.x - m2) * r2, wv.x, bv.x)));
        o.y = __uint_as_float(f2tf(fmaf((yv.y - m2) * r2, wv.y, bv.y)));
        o.z = __uint_as_float(f2tf(fmaf((yv.z - m2) * r2, wv.z, bv.z)));
        o.w = __uint_as_float(f2tf(fmaf((yv.w - m2) * r2, wv.w, bv.w)));
        *(float4*)(smb + row * PAD + col) = o;
    }
    __syncthreads();
    // GEMM3 (128x64) with GLU row pairing
    int ra = 8 * w + (lane >> 2), rg = ra + 64, kc = lane & 3;
    {
        unsigned A[8][4];
#pragma unroll
        for (int kt = 0; kt < 8; ++kt) {
            int k0 = kt * 8 + kc;
            A[kt][0] = f2tf(W3[ra * 64 + k0]);
            A[kt][1] = f2tf(W3[rg * 64 + k0]);
            A[kt][2] = f2tf(W3[ra * 64 + k0 + 4]);
            A[kt][3] = f2tf(W3[rg * 64 + k0 + 4]);
        }
        float acc[8][4];
#pragma unroll
        for (int i = 0; i < 8; ++i)
#pragma unroll
            for (int j = 0; j < 4; ++j) acc[i][j] = 0.f;
#pragma unroll
        for (int nt = 0; nt < 8; ++nt) {
            int n0 = nt * 8 + (lane >> 2);
#pragma unroll
            for (int kt = 0; kt < 8; ++kt) {
                int kr = kt * 8 + kc;
                unsigned bb0 = __float_as_uint(smb[kr * PAD + n0]);
                unsigned bb1 = __float_as_uint(smb[(kr + 4) * PAD + n0]);
                mma8(acc[nt], A[kt], bb0, bb1);
            }
        }
        float b3a = pb3[ra], b3g = pb3[rg];
        float ur[16];
#pragma unroll
        for (int nt = 0; nt < 8; ++nt) {
            float a0 = acc[nt][0] + b3a;
            float a1 = acc[nt][1] + b3a;
            float g0 = acc[nt][2] + b3g;
            float g1 = acc[nt][3] + b3g;
            ur[nt * 2]     = a0 * sigm(g0);
            ur[nt * 2 + 1] = a1 * sigm(g1);
        }
        __syncthreads();  // done reading ln2 from smb
#pragma unroll
        for (int nt = 0; nt < 8; ++nt) {
            int c0 = nt * 8 + (lane & 3) * 2;
            smb[ra * PAD + c0]     = __uint_as_float(f2tf(ur[nt * 2]));
            smb[ra * PAD + c0 + 1] = __uint_as_float(f2tf(ur[nt * 2 + 1]));
        }
        __syncthreads();
    }
    // GEMM4 (64x64): out = W4@u2 + b4 + y
    int mt = w & 3, half = w >> 2;
    int r0 = mt * 16 + (lane >> 2), r1r = r0 + 8;
    unsigned A2[8][4];
#pragma unroll
    for (int kt = 0; kt < 8; ++kt) {
        int k0 = kt * 8 + kc;
        A2[kt][0] = f2tf(W4[r0  * 64 + k0]);
        A2[kt][1] = f2tf(W4[r1r * 64 + k0]);
        A2[kt][2] = f2tf(W4[r0  * 64 + k0 + 4]);
        A2[kt][3] = f2tf(W4[r1r * 64 + k0 + 4]);
    }
    float ac2[4][4];
#pragma unroll
    for (int i = 0; i < 4; ++i)
#pragma unroll
        for (int j = 0; j < 4; ++j) ac2[i][j] = 0.f;
#pragma unroll
    for (int nt = 0; nt < 4; ++nt) {
        int n0 = half * 32 + nt * 8 + (lane >> 2);
#pragma unroll
        for (int kt = 0; kt < 8; ++kt) {
            int kr = kt * 8 + kc;
            unsigned bb0 = __float_as_uint(smb[kr * PAD + n0]);
            unsigned bb1 = __float_as_uint(smb[(kr + 4) * PAD + n0]);
            mma8(ac2[nt], A2[kt], bb0, bb1);
        }
    }
    float b40 = pb4[r0], b41 = pb4[r1r];
    float outr[16];
#pragma unroll
    for (int nt = 0; nt < 4; ++nt) {
        int c0 = half * 32 + nt * 8 + (lane & 3) * 2;
        outr[nt * 4 + 0] = ac2[nt][0] + b40 + smy[r0  * PAD + c0];
        outr[nt * 4 + 1] = ac2[nt][1] + b40 + smy[r0  * PAD + c0 + 1];
        outr[nt * 4 + 2] = ac2[nt][2] + b41 + smy[r1r * PAD + c0];
        outr[nt * 4 + 3] = ac2[nt][3] + b41 + smy[r1r * PAD + c0 + 1];
    }
    __syncthreads();  // done reading u2 from smb
#pragma unroll
    for (int nt = 0; nt < 4; ++nt) {
        int c0 = half * 32 + nt * 8 + (lane & 3) * 2;
        smb[r0  * PAD + c0]     = outr[nt * 4 + 0];
        smb[r0  * PAD + c0 + 1] = outr[nt * 4 + 1];
        smb[r1r * PAD + c0]     = outr[nt * 4 + 2];
        smb[r1r * PAD + c0 + 1] = outr[nt * 4 + 3];
    }
    __syncthreads();
#pragma unroll
    for (int it = 0; it < 4; ++it) {
        int e = (tid + 256 * it) * 4;
        int row = e >> 6, col = e & 63;
        *(float4*)(io + base + (size_t)row * FSZ + col) = *(float4*)(smb + row * PAD + col);
    }
}

// ---------------- launch ----------------
extern "C" void kernel_launch(void* const* d_in, const int* in_sizes, int n_in,
                              void* d_out, int out_size) {
    const float* x   = (const float*)d_in[0];
    const float* l1w = (const float*)d_in[1];
    const float* l1b = (const float*)d_in[2];
    const float* l2w = (const float*)d_in[3];
    const float* l2b = (const float*)d_in[4];
    const float* W1  = (const float*)d_in[5];
    const float* b1  = (const float*)d_in[6];
    const float* dww = (const float*)d_in[7];
    const float* dwb = (const float*)d_in[8];
    const float* aw1 = (const float*)d_in[9];
    const float* ab1 = (const float*)d_in[10];
    const float* aw2 = (const float*)d_in[11];
    const float* ab2 = (const float*)d_in[12];
    const float* W2  = (const float*)d_in[13];
    const float* b2  = (const float*)d_in[14];
    const float* W3  = (const float*)d_in[15];
    const float* b3  = (const float*)d_in[16];
    const float* W4  = (const float*)d_in[17];
    const float* b4  = (const float*)d_in[18];
    float* out = (float*)d_out;

    k_zero  <<<1, 256>>>();
    k_stats1<<<NB * 512, 256>>>(x);
    k_br1   <<<NB * 1024, 256>>>(x, l1w, l1b, W1, b1, dww, dwb);
    k_y     <<<NB * 1024, 256>>>(x, W2, b2, aw1, ab1, aw2, ab2, out);
    k_br2   <<<NB * 1024, 256>>>(l2w, l2b, W3, b3, W4, b4, out);
}

// round 12
// speedup vs baseline: 1.9049x; 1.4357x over previous
#include <cuda_runtime.h>
#include <cuda_fp16.h>
#include <math.h>

#define NB   4
#define NC   64
#define FSZ  65536            // F*S
#define CFS  4194304          // C*F*S
#define TPIX 64               // pixels per tile
#define PAD  72               // smem row stride (72 mod 32 == 8 -> conflict free)
#define EPSV 1e-5

// ---------------- scratch (no allocs allowed) ----------------
__device__ double g_acc[16];                 // per batch: {sx, sxx, sy, syy}
__device__ float  g_p[NB * NC];              // post-GLU channel sums
__device__ __align__(16) __half g_u[(size_t)NB * CFS];  // post-GLU activations, fp16, [b][ch][px]
// precomputed tf32 A-fragments, [kt*256 + tid] (identical for every block)
__device__ uint4  g_W1f[8 * 256];            // br1 role (128x64, GLU pairing)
__device__ uint4  g_W2f[8 * 256];            // k_y role (64x64)
__device__ uint4  g_W3f[8 * 256];            // br2 GEMM3 role
__device__ uint4  g_W4f[8 * 256];            // br2 GEMM4 role

// ---------------- helpers ----------------
__device__ __forceinline__ unsigned f2tf(float f) {
    unsigned u;
    asm("cvt.rna.tf32.f32 %0, %1;" : "=r"(u) : "f"(f));
    return u;
}
__device__ __forceinline__ void mma8(float acc[4], unsigned a0, unsigned a1,
                                     unsigned a2, unsigned a3,
                                     unsigned b0, unsigned b1) {
    asm volatile(
        "mma.sync.aligned.m16n8k8.row.col.f32.tf32.tf32.f32 "
        "{%0,%1,%2,%3},{%4,%5,%6,%7},{%8,%9},{%0,%1,%2,%3};\n"
        : "+f"(acc[0]), "+f"(acc[1]), "+f"(acc[2]), "+f"(acc[3])
        : "r"(a0), "r"(a1), "r"(a2), "r"(a3), "r"(b0), "r"(b1));
}
__device__ __forceinline__ float sigm(float v) { return 1.f / (1.f + __expf(-v)); }

// ---------------- K0: zero accumulators + precompute weight fragments ----------------
__global__ void k_init(const float* __restrict__ W1, const float* __restrict__ W2,
                       const float* __restrict__ W3, const float* __restrict__ W4) {
    int tid = threadIdx.x, w = tid >> 5, lane = tid & 31;
    int blk = blockIdx.x;
    if (blk == 0) {
        if (tid < 16) g_acc[tid] = 0.0;
        g_p[tid] = 0.f;
        return;
    }
    int gq = lane >> 2, kc = lane & 3;
    if (blk == 1 || blk == 3) {            // br-role fragments: rows (8w+gq, +64)
        const float* W = (blk == 1) ? W1 : W3;
        uint4* dst = (blk == 1) ? g_W1f : g_W3f;
        int ra = 8 * w + gq, rg = ra + 64;
#pragma unroll
        for (int kt = 0; kt < 8; ++kt) {
            int k0 = kt * 8 + kc;
            uint4 v;
            v.x = f2tf(W[ra * 64 + k0]);
            v.y = f2tf(W[rg * 64 + k0]);
            v.z = f2tf(W[ra * 64 + k0 + 4]);
            v.w = f2tf(W[rg * 64 + k0 + 4]);
            dst[kt * 256 + tid] = v;
        }
    } else {                                // y-role fragments: rows (mt*16+gq, +8)
        const float* W = (blk == 2) ? W2 : W4;
        uint4* dst = (blk == 2) ? g_W2f : g_W4f;
        int mt = w & 3;
        int r0 = mt * 16 + gq, r1 = r0 + 8;
#pragma unroll
        for (int kt = 0; kt < 8; ++kt) {
            int k0 = kt * 8 + kc;
            uint4 v;
            v.x = f2tf(W[r0 * 64 + k0]);
            v.y = f2tf(W[r1 * 64 + k0]);
            v.z = f2tf(W[r0 * 64 + k0 + 4]);
            v.w = f2tf(W[r1 * 64 + k0 + 4]);
            dst[kt * 256 + tid] = v;
        }
    }
}

// ---------------- K1: LN1 stats ----------------
__global__ __launch_bounds__(256) void k_stats1(const float* __restrict__ x) {
    int bat = blockIdx.x >> 9;
    int chunk = blockIdx.x & 511;
    size_t base = (size_t)bat * CFS + (size_t)chunk * 8192;
    float s = 0.f, ss = 0.f;
#pragma unroll
    for (int it = 0; it < 8; ++it) {
        float4 v = *(const float4*)(x + base + (size_t)(threadIdx.x + 256 * it) * 4);
        s  += (v.x + v.y) + (v.z + v.w);
        ss += (v.x * v.x + v.y * v.y) + (v.z * v.z + v.w * v.w);
    }
#pragma unroll
    for (int o = 16; o; o >>= 1) {
        s  += __shfl_xor_sync(0xffffffffu, s,  o);
        ss += __shfl_xor_sync(0xffffffffu, ss, o);
    }
    __shared__ float red[16];
    int w = threadIdx.x >> 5, lane = threadIdx.x & 31;
    if (!lane) { red[w] = s; red[8 + w] = ss; }
    __syncthreads();
    if (threadIdx.x == 0) {
        float S = 0.f, SS = 0.f;
#pragma unroll
        for (int i = 0; i < 8; ++i) { S += red[i]; SS += red[8 + i]; }
        atomicAdd(&g_acc[bat * 4 + 0], (double)S);
        atomicAdd(&g_acc[bat * 4 + 1], (double)SS);
    }
}

// ---------------- K2: LN1 -> GEMM1 -> dw affine -> GLU -> u(fp16), accumulate p ----------------
__global__ __launch_bounds__(256) void k_br1(
    const float* __restrict__ x,  const float* __restrict__ lnw,
    const float* __restrict__ lnb,
    const float* __restrict__ pb1, const float* __restrict__ dww,
    const float* __restrict__ dwb) {
    __shared__ float sm[NC * PAD];
    __shared__ float st[2];
    int tid = threadIdx.x, w = tid >> 5, lane = tid & 31;
    int bat = blockIdx.x >> 10;
    int tile = blockIdx.x & 1023;
    size_t base  = (size_t)bat * CFS + (size_t)tile * TPIX;
    size_t pbase = (size_t)tile * TPIX;                      // LN params: NO batch dim
    if (tid == 0) {
        double m = g_acc[bat * 4 + 0] * (1.0 / (double)CFS);
        double v = g_acc[bat * 4 + 1] * (1.0 / (double)CFS) - m * m;
        st[0] = (float)m;
        st[1] = (float)(1.0 / sqrt(v + EPSV));
    }
    __syncthreads();
    float m1 = st[0], r1 = st[1];
#pragma unroll
    for (int it = 0; it < 4; ++it) {
        int e = (tid + 256 * it) * 4;
        int row = e >> 6, col = e & 63;
        size_t g  = base  + (size_t)row * FSZ + col;
        size_t gp = pbase + (size_t)row * FSZ + col;
        float4 xv = *(const float4*)(x + g);
        float4 wv = *(const float4*)(lnw + gp);
        float4 bv = *(const float4*)(lnb + gp);
        float4 o;
        o.x = __uint_as_float(f2tf(fmaf((xv.x - m1) * r1, wv.x, bv.x)));
        o.y = __uint_as_float(f2tf(fmaf((xv.y - m1) * r1, wv.y, bv.y)));
        o.z = __uint_as_float(f2tf(fmaf((xv.z - m1) * r1, wv.z, bv.z)));
        o.w = __uint_as_float(f2tf(fmaf((xv.w - m1) * r1, wv.w, bv.w)));
        *(float4*)(sm + row * PAD + col) = o;
    }
    __syncthreads();
    // A fragments: precomputed, coalesced
    int ra = 8 * w + (lane >> 2), rg = ra + 64;
    uint4 A[8];
#pragma unroll
    for (int kt = 0; kt < 8; ++kt) A[kt] = g_W1f[kt * 256 + tid];
    float acc[8][4];
#pragma unroll
    for (int i = 0; i < 8; ++i)
#pragma unroll
        for (int j = 0; j < 4; ++j) acc[i][j] = 0.f;
    int kc = lane & 3;
#pragma unroll
    for (int nt = 0; nt < 8; ++nt) {
        int n0 = nt * 8 + (lane >> 2);
#pragma unroll
        for (int kt = 0; kt < 8; ++kt) {
            int kr = kt * 8 + kc;
            unsigned bb0 = __float_as_uint(sm[kr * PAD + n0]);
            unsigned bb1 = __float_as_uint(sm[(kr + 4) * PAD + n0]);
            mma8(acc[nt], A[kt].x, A[kt].y, A[kt].z, A[kt].w, bb0, bb1);
        }
    }
    // epilogue: +b1, dw affine, GLU; a/g pair is in-register
    float b1a = pb1[ra], b1g = pb1[rg];
    float dwa = dww[ra], dba = dwb[ra], dwg = dww[rg], dbg = dwb[rg];
    float ur[16];
    float psum = 0.f;
#pragma unroll
    for (int nt = 0; nt < 8; ++nt) {
        float a0 = fmaf(acc[nt][0] + b1a, dwa, dba);
        float a1 = fmaf(acc[nt][1] + b1a, dwa, dba);
        float g0 = fmaf(acc[nt][2] + b1g, dwg, dbg);
        float g1 = fmaf(acc[nt][3] + b1g, dwg, dbg);
        float u0 = a0 * sigm(g0);
        float u1 = a1 * sigm(g1);
        ur[nt * 2] = u0; ur[nt * 2 + 1] = u1;
        psum += u0 + u1;
    }
    psum += __shfl_xor_sync(0xffffffffu, psum, 1);
    psum += __shfl_xor_sync(0xffffffffu, psum, 2);
    if ((lane & 3) == 0) atomicAdd(&g_p[bat * 64 + ra], psum);
    __syncthreads();
#pragma unroll
    for (int nt = 0; nt < 8; ++nt) {
        int c0 = nt * 8 + (lane & 3) * 2;
        sm[ra * PAD + c0]     = ur[nt * 2];
        sm[ra * PAD + c0 + 1] = ur[nt * 2 + 1];
    }
    __syncthreads();
    // write u as fp16, same [ch][px] geometry (uint2 = 4 halves)
#pragma unroll
    for (int it = 0; it < 4; ++it) {
        int e = (tid + 256 * it) * 4;
        int row = e >> 6, col = e & 63;
        float4 v = *(float4*)(sm + row * PAD + col);
        __half2 h0 = __floats2half2_rn(v.x, v.y);
        __half2 h1 = __floats2half2_rn(v.z, v.w);
        uint2 o;
        o.x = *(unsigned*)&h0;
        o.y = *(unsigned*)&h1;
        *(uint2*)(g_u + base + (size_t)row * FSZ + col) = o;
    }
}

// ---------------- K3: SE gate (warp-coop, fused) + y = W2@(u*s)+b2+x ; LN2 stats ----------------
__global__ __launch_bounds__(256) void k_y(
    const float* __restrict__ x,
    const float* __restrict__ pb2,
    const float* __restrict__ aw1, const float* __restrict__ ab1,
    const float* __restrict__ aw2, const float* __restrict__ ab2,
    float* __restrict__ yo) {
    __shared__ float smu[NC * PAD];
    __shared__ float smx[NC * PAD];
    __shared__ float ssg[64], sp[64], sh[64];
    __shared__ float red[16];
    int tid = threadIdx.x, w = tid >> 5, lane = tid & 31;
    int bat = blockIdx.x >> 10;
    int tile = blockIdx.x & 1023;
    size_t base = (size_t)bat * CFS + (size_t)tile * TPIX;
    // ---- SE gate, warp-cooperative: 4-lane group (w, lane>>2) owns channel c ----
    if (tid < 64) sp[tid] = g_p[bat * 64 + tid] * (1.f / 65536.f);
    __syncthreads();
    {
        int gq = lane >> 2, t = lane & 3;
        int c = 8 * w + gq;
        const float4* a1 = (const float4*)(aw1 + c * 64 + t * 16);
        float part = 0.f;
#pragma unroll
        for (int q = 0; q < 4; ++q) {
            float4 wv = a1[q];
            int j = t * 16 + q * 4;
            part += wv.x * sp[j] + wv.y * sp[j + 1] + wv.z * sp[j + 2] + wv.w * sp[j + 3];
        }
        part += __shfl_xor_sync(0xffffffffu, part, 1);
        part += __shfl_xor_sync(0xffffffffu, part, 2);
        if (t == 0) sh[c] = fmaxf(part + ab1[c], 0.f);
        __syncthreads();
        const float4* a2 = (const float4*)(aw2 + c * 64 + t * 16);
        part = 0.f;
#pragma unroll
        for (int q = 0; q < 4; ++q) {
            float4 wv = a2[q];
            int j = t * 16 + q * 4;
            part += wv.x * sh[j] + wv.y * sh[j + 1] + wv.z * sh[j + 2] + wv.w * sh[j + 3];
        }
        part += __shfl_xor_sync(0xffffffffu, part, 1);
        part += __shfl_xor_sync(0xffffffffu, part, 2);
        if (t == 0) ssg[c] = sigm(part + ab2[c]);
    }
    __syncthreads();
#pragma unroll
    for (int it = 0; it < 4; ++it) {
        int e = (tid + 256 * it) * 4;
        int row = e >> 6, col = e & 63;
        size_t g = base + (size_t)row * FSZ + col;
        uint2 uv = *(const uint2*)(g_u + g);
        float2 f0 = __half22float2(*(__half2*)&uv.x);
        float2 f1 = __half22float2(*(__half2*)&uv.y);
        float4 xv = *(const float4*)(x + g);
        float sg = ssg[row];
        float4 o;
        o.x = __uint_as_float(f2tf(f0.x * sg));
        o.y = __uint_as_float(f2tf(f0.y * sg));
        o.z = __uint_as_float(f2tf(f1.x * sg));
        o.w = __uint_as_float(f2tf(f1.y * sg));
        *(float4*)(smu + row * PAD + col) = o;
        *(float4*)(smx + row * PAD + col) = xv;
    }
    __syncthreads();
    int mt = w & 3, half = w >> 2;
    int r0 = mt * 16 + (lane >> 2), r1r = r0 + 8, kc = lane & 3;
    uint4 A[8];
#pragma unroll
    for (int kt = 0; kt < 8; ++kt) A[kt] = g_W2f[kt * 256 + tid];
    float acc[4][4];
#pragma unroll
    for (int i = 0; i < 4; ++i)
#pragma unroll
        for (int j = 0; j < 4; ++j) acc[i][j] = 0.f;
#pragma unroll
    for (int nt = 0; nt < 4; ++nt) {
        int n0 = half * 32 + nt * 8 + (lane >> 2);
#pragma unroll
        for (int kt = 0; kt < 8; ++kt) {
            int kr = kt * 8 + kc;
            unsigned bb0 = __float_as_uint(smu[kr * PAD + n0]);
            unsigned bb1 = __float_as_uint(smu[(kr + 4) * PAD + n0]);
            mma8(acc[nt], A[kt].x, A[kt].y, A[kt].z, A[kt].w, bb0, bb1);
        }
    }
    float bc0 = pb2[r0], bc1 = pb2[r1r];
    float yr[16];
    float sy = 0.f, syy = 0.f;
#pragma unroll
    for (int nt = 0; nt < 4; ++nt) {
        int c0 = half * 32 + nt * 8 + (lane & 3) * 2;
        float y00 = acc[nt][0] + bc0 + smx[r0  * PAD + c0];
        float y01 = acc[nt][1] + bc0 + smx[r0  * PAD + c0 + 1];
        float y10 = acc[nt][2] + bc1 + smx[r1r * PAD + c0];
        float y11 = acc[nt][3] + bc1 + smx[r1r * PAD + c0 + 1];
        yr[nt * 4 + 0] = y00; yr[nt * 4 + 1] = y01;
        yr[nt * 4 + 2] = y10; yr[nt * 4 + 3] = y11;
        sy  += (y00 + y01) + (y10 + y11);
        syy += (y00 * y00 + y01 * y01) + (y10 * y10 + y11 * y11);
    }
    __syncthreads();   // all warps done reading smu
#pragma unroll
    for (int nt = 0; nt < 4; ++nt) {
        int c0 = half * 32 + nt * 8 + (lane & 3) * 2;
        smu[r0  * PAD + c0]     = yr[nt * 4 + 0];
        smu[r0  * PAD + c0 + 1] = yr[nt * 4 + 1];
        smu[r1r * PAD + c0]     = yr[nt * 4 + 2];
        smu[r1r * PAD + c0 + 1] = yr[nt * 4 + 3];
    }
#pragma unroll
    for (int o = 16; o; o >>= 1) {
        sy  += __shfl_xor_sync(0xffffffffu, sy,  o);
        syy += __shfl_xor_sync(0xffffffffu, syy, o);
    }
    if (!lane) { red[w] = sy; red[8 + w] = syy; }
    __syncthreads();
    if (tid == 0) {
        float S = 0.f, SS = 0.f;
#pragma unroll
        for (int i = 0; i < 8; ++i) { S += red[i]; SS += red[8 + i]; }
        atomicAdd(&g_acc[bat * 4 + 2], (double)S);
        atomicAdd(&g_acc[bat * 4 + 3], (double)SS);
    }
#pragma unroll
    for (int it = 0; it < 4; ++it) {
        int e = (tid + 256 * it) * 4;
        int row = e >> 6, col = e & 63;
        *(float4*)(yo + base + (size_t)row * FSZ + col) = *(float4*)(smu + row * PAD + col);
    }
}

// ---------------- K4: LN2 -> GEMM3 -> GLU -> GEMM4 -> +y ----------------
__global__ __launch_bounds__(256) void k_br2(
    const float* __restrict__ lnw, const float* __restrict__ lnb,
    const float* __restrict__ pb3, const float* __restrict__ pb4,
    float* __restrict__ io) {
    __shared__ float smy[NC * PAD];
    __shared__ float smb[NC * PAD];
    __shared__ float st[2];
    int tid = threadIdx.x, w = tid >> 5, lane = tid & 31;
    int bat = blockIdx.x >> 10;
    int tile = blockIdx.x & 1023;
    size_t base  = (size_t)bat * CFS + (size_t)tile * TPIX;
    size_t pbase = (size_t)tile * TPIX;                      // LN params: NO batch dim
    if (tid == 0) {
        double m = g_acc[bat * 4 + 2] * (1.0 / (double)CFS);
        double v = g_acc[bat * 4 + 3] * (1.0 / (double)CFS) - m * m;
        st[0] = (float)m;
        st[1] = (float)(1.0 / sqrt(v + EPSV));
    }
    __syncthreads();
    float m2 = st[0], r2 = st[1];
#pragma unroll
    for (int it = 0; it < 4; ++it) {
        int e = (tid + 256 * it) * 4;
        int row = e >> 6, col = e & 63;
        size_t g  = base  + (size_t)row * FSZ + col;
        size_t gp = pbase + (size_t)row * FSZ + col;
        float4 yv = *(const float4*)(io + g);
        float4 wv = *(const float4*)(lnw + gp);
        float4 bv = *(const float4*)(lnb + gp);
        *(float4*)(smy + row * PAD + col) = yv;
        float4 o;
        o.x = __uint_as_float(f2tf(fmaf((yv.x - m2) * r2, wv.x, bv.x)));
        o.y = __uint_as_float(f2tf(fmaf((yv.y - m2) * r2, wv.y, bv.y)));
        o.z = __uint_as_float(f2tf(fmaf((yv.z - m2) * r2, wv.z, bv.z)));
        o.w = __uint_as_float(f2tf(fmaf((yv.w - m2) * r2, wv.w, bv.w)));
        *(float4*)(smb + row * PAD + col) = o;
    }
    __syncthreads();
    // GEMM3 (128x64) with GLU row pairing
    int ra = 8 * w + (lane >> 2), rg = ra + 64, kc = lane & 3;
    {
        uint4 A[8];
#pragma unroll
        for (int kt = 0; kt < 8; ++kt) A[kt] = g_W3f[kt * 256 + tid];
        float acc[8][4];
#pragma unroll
        for (int i = 0; i < 8; ++i)
#pragma unroll
            for (int j = 0; j < 4; ++j) acc[i][j] = 0.f;
#pragma unroll
        for (int nt = 0; nt < 8; ++nt) {
            int n0 = nt * 8 + (lane >> 2);
#pragma unroll
            for (int kt = 0; kt < 8; ++kt) {
                int kr = kt * 8 + kc;
                unsigned bb0 = __float_as_uint(smb[kr * PAD + n0]);
                unsigned bb1 = __float_as_uint(smb[(kr + 4) * PAD + n0]);
                mma8(acc[nt], A[kt].x, A[kt].y, A[kt].z, A[kt].w, bb0, bb1);
            }
        }
        float b3a = pb3[ra], b3g = pb3[rg];
        float ur[16];
#pragma unroll
        for (int nt = 0; nt < 8; ++nt) {
            float a0 = acc[nt][0] + b3a;
            float a1 = acc[nt][1] + b3a;
            float g0 = acc[nt][2] + b3g;
            float g1 = acc[nt][3] + b3g;
            ur[nt * 2]     = a0 * sigm(g0);
            ur[nt * 2 + 1] = a1 * sigm(g1);
        }
        __syncthreads();  // done reading ln2 from smb
#pragma unroll
        for (int nt = 0; nt < 8; ++nt) {
            int c0 = nt * 8 + (lane & 3) * 2;
            smb[ra * PAD + c0]     = __uint_as_float(f2tf(ur[nt * 2]));
            smb[ra * PAD + c0 + 1] = __uint_as_float(f2tf(ur[nt * 2 + 1]));
        }
        __syncthreads();
    }
    // GEMM4 (64x64): out = W4@u2 + b4 + y
    int mt = w & 3, half = w >> 2;
    int r0 = mt * 16 + (lane >> 2), r1r = r0 + 8;
    uint4 A2[8];
#pragma unroll
    for (int kt = 0; kt < 8; ++kt) A2[kt] = g_W4f[kt * 256 + tid];
    float ac2[4][4];
#pragma unroll
    for (int i = 0; i < 4; ++i)
#pragma unroll
        for (int j = 0; j < 4; ++j) ac2[i][j] = 0.f;
#pragma unroll
    for (int nt = 0; nt < 4; ++nt) {
        int n0 = half * 32 + nt * 8 + (lane >> 2);
#pragma unroll
        for (int kt = 0; kt < 8; ++kt) {
            int kr = kt * 8 + kc;
            unsigned bb0 = __float_as_uint(smb[kr * PAD + n0]);
            unsigned bb1 = __float_as_uint(smb[(kr + 4) * PAD + n0]);
            mma8(ac2[nt], A2[kt].x, A2[kt].y, A2[kt].z, A2[kt].w, bb0, bb1);
        }
    }
    float b40 = pb4[r0], b41 = pb4[r1r];
    float outr[16];
#pragma unroll
    for (int nt = 0; nt < 4; ++nt) {
        int c0 = half * 32 + nt * 8 + (lane & 3) * 2;
        outr[nt * 4 + 0] = ac2[nt][0] + b40 + smy[r0  * PAD + c0];
        outr[nt * 4 + 1] = ac2[nt][1] + b40 + smy[r0  * PAD + c0 + 1];
        outr[nt * 4 + 2] = ac2[nt][2] + b41 + smy[r1r * PAD + c0];
        outr[nt * 4 + 3] = ac2[nt][3] + b41 + smy[r1r * PAD + c0 + 1];
    }
    __syncthreads();  // done reading u2 from smb
#pragma unroll
    for (int nt = 0; nt < 4; ++nt) {
        int c0 = half * 32 + nt * 8 + (lane & 3) * 2;
        smb[r0  * PAD + c0]     = outr[nt * 4 + 0];
        smb[r0  * PAD + c0 + 1] = outr[nt * 4 + 1];
        smb[r1r * PAD + c0]     = outr[nt * 4 + 2];
        smb[r1r * PAD + c0 + 1] = outr[nt * 4 + 3];
    }
    __syncthreads();
#pragma unroll
    for (int it = 0; it < 4; ++it) {
        int e = (tid + 256 * it) * 4;
        int row = e >> 6, col = e & 63;
        *(float4*)(io + base + (size_t)row * FSZ + col) = *(float4*)(smb + row * PAD + col);
    }
}

// ---------------- launch ----------------
extern "C" void kernel_launch(void* const* d_in, const int* in_sizes, int n_in,
                              void* d_out, int out_size) {
    const float* x   = (const float*)d_in[0];
    const float* l1w = (const float*)d_in[1];
    const float* l1b = (const float*)d_in[2];
    const float* l2w = (const float*)d_in[3];
    const float* l2b = (const float*)d_in[4];
    const float* W1  = (const float*)d_in[5];
    const float* b1  = (const float*)d_in[6];
    const float* dww = (const float*)d_in[7];
    const float* dwb = (const float*)d_in[8];
    const float* aw1 = (const float*)d_in[9];
    const float* ab1 = (const float*)d_in[10];
    const float* aw2 = (const float*)d_in[11];
    const float* ab2 = (const float*)d_in[12];
    const float* W2  = (const float*)d_in[13];
    const float* b2  = (const float*)d_in[14];
    const float* W3  = (const float*)d_in[15];
    const float* b3  = (const float*)d_in[16];
    const float* W4  = (const float*)d_in[17];
    const float* b4  = (const float*)d_in[18];
    float* out = (float*)d_out;

    k_init  <<<5, 256>>>(W1, W2, W3, W4);
    k_stats1<<<NB * 512, 256>>>(x);
    k_br1   <<<NB * 1024, 256>>>(x, l1w, l1b, b1, dww, dwb);
    k_y     <<<NB * 1024, 256>>>(x, b2, aw1, ab1, aw2, ab2, out);
    k_br2   <<<NB * 1024, 256>>>(l2w, l2b, b3, b4, out);
}

// round 13
// speedup vs baseline: 1.9752x; 1.0369x over previous
#include <cuda_runtime.h>
#include <cuda_fp16.h>
#include <math.h>

#define NB   4
#define NC   64
#define FSZ  65536            // F*S
#define CFS  4194304          // C*F*S
#define TPIX 64               // pixels per tile
#define PAD  72               // smem row stride (72 mod 32 == 8 -> conflict free)
#define EPSV 1e-5

// ---------------- scratch (no allocs allowed) ----------------
__device__ double g_acc[16];                 // per batch: {sx, sxx, sy, syy}
__device__ float  g_p[NB * NC];              // post-GLU channel sums
__device__ __align__(16) __half g_u[(size_t)NB * CFS];  // post-GLU activations, fp16, [b][ch][px]
// precomputed tf32 A-fragments, [kt*256 + tid] (identical for every block)
__device__ uint4  g_W1f[8 * 256];
__device__ uint4  g_W2f[8 * 256];
__device__ uint4  g_W3f[8 * 256];
__device__ uint4  g_W4f[8 * 256];

// ---------------- helpers ----------------
__device__ __forceinline__ unsigned f2tf(float f) {
    unsigned u;
    asm("cvt.rna.tf32.f32 %0, %1;" : "=r"(u) : "f"(f));
    return u;
}
__device__ __forceinline__ void mma8(float acc[4], unsigned a0, unsigned a1,
                                     unsigned a2, unsigned a3,
                                     unsigned b0, unsigned b1) {
    asm volatile(
        "mma.sync.aligned.m16n8k8.row.col.f32.tf32.tf32.f32 "
        "{%0,%1,%2,%3},{%4,%5,%6,%7},{%8,%9},{%0,%1,%2,%3};\n"
        : "+f"(acc[0]), "+f"(acc[1]), "+f"(acc[2]), "+f"(acc[3])
        : "r"(a0), "r"(a1), "r"(a2), "r"(a3), "r"(b0), "r"(b1));
}
__device__ __forceinline__ float sigm(float v) { return 1.f / (1.f + __expf(-v)); }

// ---------------- K0: zero accumulators + precompute weight fragments ----------------
__global__ void k_init(const float* __restrict__ W1, const float* __restrict__ W2,
                       const float* __restrict__ W3, const float* __restrict__ W4) {
    int tid = threadIdx.x, w = tid >> 5, lane = tid & 31;
    int blk = blockIdx.x;
    if (blk == 0) {
        if (tid < 16) g_acc[tid] = 0.0;
        g_p[tid] = 0.f;
        return;
    }
    int gq = lane >> 2, kc = lane & 3;
    if (blk == 1 || blk == 3) {            // br-role fragments: rows (8w+gq, +64)
        const float* W = (blk == 1) ? W1 : W3;
        uint4* dst = (blk == 1) ? g_W1f : g_W3f;
        int ra = 8 * w + gq, rg = ra + 64;
#pragma unroll
        for (int kt = 0; kt < 8; ++kt) {
            int k0 = kt * 8 + kc;
            uint4 v;
            v.x = f2tf(W[ra * 64 + k0]);
            v.y = f2tf(W[rg * 64 + k0]);
            v.z = f2tf(W[ra * 64 + k0 + 4]);
            v.w = f2tf(W[rg * 64 + k0 + 4]);
            dst[kt * 256 + tid] = v;
        }
    } else {                                // y-role fragments: rows (mt*16+gq, +8)
        const float* W = (blk == 2) ? W2 : W4;
        uint4* dst = (blk == 2) ? g_W2f : g_W4f;
        int mt = w & 3;
        int r0 = mt * 16 + gq, r1 = r0 + 8;
#pragma unroll
        for (int kt = 0; kt < 8; ++kt) {
            int k0 = kt * 8 + kc;
            uint4 v;
            v.x = f2tf(W[r0 * 64 + k0]);
            v.y = f2tf(W[r1 * 64 + k0]);
            v.z = f2tf(W[r0 * 64 + k0 + 4]);
            v.w = f2tf(W[r1 * 64 + k0 + 4]);
            dst[kt * 256 + tid] = v;
        }
    }
}

// ---------------- K1: LN1 stats ----------------
__global__ __launch_bounds__(256) void k_stats1(const float* __restrict__ x) {
    int bat = blockIdx.x >> 9;
    int chunk = blockIdx.x & 511;
    size_t base = (size_t)bat * CFS + (size_t)chunk * 8192;
    float s = 0.f, ss = 0.f;
#pragma unroll
    for (int it = 0; it < 8; ++it) {
        float4 v = *(const float4*)(x + base + (size_t)(threadIdx.x + 256 * it) * 4);
        s  += (v.x + v.y) + (v.z + v.w);
        ss += (v.x * v.x + v.y * v.y) + (v.z * v.z + v.w * v.w);
    }
#pragma unroll
    for (int o = 16; o; o >>= 1) {
        s  += __shfl_xor_sync(0xffffffffu, s,  o);
        ss += __shfl_xor_sync(0xffffffffu, ss, o);
    }
    __shared__ float red[16];
    int w = threadIdx.x >> 5, lane = threadIdx.x & 31;
    if (!lane) { red[w] = s; red[8 + w] = ss; }
    __syncthreads();
    if (threadIdx.x == 0) {
        float S = 0.f, SS = 0.f;
#pragma unroll
        for (int i = 0; i < 8; ++i) { S += red[i]; SS += red[8 + i]; }
        atomicAdd(&g_acc[bat * 4 + 0], (double)S);
        atomicAdd(&g_acc[bat * 4 + 1], (double)SS);
    }
}

// ---------------- K2: LN1 -> GEMM1 -> dw affine -> GLU -> u(fp16), accumulate p ----------------
__global__ __launch_bounds__(256, 4) void k_br1(
    const float* __restrict__ x,  const float* __restrict__ lnw,
    const float* __restrict__ lnb,
    const float* __restrict__ pb1, const float* __restrict__ dww,
    const float* __restrict__ dwb) {
    __shared__ float sm[NC * PAD];
    __shared__ float st[2];
    int tid = threadIdx.x, w = tid >> 5, lane = tid & 31;
    int bat = blockIdx.x >> 10;
    int tile = blockIdx.x & 1023;
    size_t base  = (size_t)bat * CFS + (size_t)tile * TPIX;
    size_t pbase = (size_t)tile * TPIX;                      // LN params: NO batch dim
    if (tid == 0) {
        double m = g_acc[bat * 4 + 0] * (1.0 / (double)CFS);
        double v = g_acc[bat * 4 + 1] * (1.0 / (double)CFS) - m * m;
        st[0] = (float)m;
        st[1] = (float)(1.0 / sqrt(v + EPSV));
    }
    __syncthreads();
    float m1 = st[0], r1 = st[1];
#pragma unroll
    for (int it = 0; it < 4; ++it) {
        int e = (tid + 256 * it) * 4;
        int row = e >> 6, col = e & 63;
        size_t g  = base  + (size_t)row * FSZ + col;
        size_t gp = pbase + (size_t)row * FSZ + col;
        float4 xv = *(const float4*)(x + g);
        float4 wv = *(const float4*)(lnw + gp);
        float4 bv = *(const float4*)(lnb + gp);
        float4 o;
        o.x = __uint_as_float(f2tf(fmaf((xv.x - m1) * r1, wv.x, bv.x)));
        o.y = __uint_as_float(f2tf(fmaf((xv.y - m1) * r1, wv.y, bv.y)));
        o.z = __uint_as_float(f2tf(fmaf((xv.z - m1) * r1, wv.z, bv.z)));
        o.w = __uint_as_float(f2tf(fmaf((xv.w - m1) * r1, wv.w, bv.w)));
        *(float4*)(sm + row * PAD + col) = o;
    }
    __syncthreads();
    // GEMM1, kt-outer: one A fragment live at a time
    int gq = lane >> 2, kc = lane & 3;
    int ra = 8 * w + gq, rg = ra + 64;
    float acc[8][4];
#pragma unroll
    for (int i = 0; i < 8; ++i)
#pragma unroll
        for (int j = 0; j < 4; ++j) acc[i][j] = 0.f;
#pragma unroll
    for (int kt = 0; kt < 8; ++kt) {
        uint4 A = g_W1f[kt * 256 + tid];
        int kr = kt * 8 + kc;
#pragma unroll
        for (int nt = 0; nt < 8; ++nt) {
            int n0 = nt * 8 + gq;
            unsigned bb0 = __float_as_uint(sm[kr * PAD + n0]);
            unsigned bb1 = __float_as_uint(sm[(kr + 4) * PAD + n0]);
            mma8(acc[nt], A.x, A.y, A.z, A.w, bb0, bb1);
        }
    }
    // epilogue: +b1, dw affine, GLU; write u directly (acc stays live across sync)
    float b1a = pb1[ra], b1g = pb1[rg];
    float dwa = dww[ra], dba = dwb[ra], dwg = dww[rg], dbg = dwb[rg];
    __syncthreads();   // all warps done reading sm
    float psum = 0.f;
#pragma unroll
    for (int nt = 0; nt < 8; ++nt) {
        int c0 = nt * 8 + kc * 2;
        float a0 = fmaf(acc[nt][0] + b1a, dwa, dba);
        float a1 = fmaf(acc[nt][1] + b1a, dwa, dba);
        float g0 = fmaf(acc[nt][2] + b1g, dwg, dbg);
        float g1 = fmaf(acc[nt][3] + b1g, dwg, dbg);
        float u0 = a0 * sigm(g0);
        float u1 = a1 * sigm(g1);
        psum += u0 + u1;
        *(float2*)(sm + ra * PAD + c0) = make_float2(u0, u1);
    }
    psum += __shfl_xor_sync(0xffffffffu, psum, 1);
    psum += __shfl_xor_sync(0xffffffffu, psum, 2);
    if (kc == 0) atomicAdd(&g_p[bat * 64 + ra], psum);
    __syncthreads();
    // write u as fp16, [ch][px] geometry (uint2 = 4 halves)
#pragma unroll
    for (int it = 0; it < 4; ++it) {
        int e = (tid + 256 * it) * 4;
        int row = e >> 6, col = e & 63;
        float4 v = *(float4*)(sm + row * PAD + col);
        __half2 h0 = __floats2half2_rn(v.x, v.y);
        __half2 h1 = __floats2half2_rn(v.z, v.w);
        uint2 o;
        o.x = *(unsigned*)&h0;
        o.y = *(unsigned*)&h1;
        *(uint2*)(g_u + base + (size_t)row * FSZ + col) = o;
    }
}

// ---------------- K3: SE gate (warp-coop, fused) + y = W2@(u*s)+b2+x ; LN2 stats ----------------
__global__ __launch_bounds__(256, 5) void k_y(
    const float* __restrict__ x,
    const float* __restrict__ pb2,
    const float* __restrict__ aw1, const float* __restrict__ ab1,
    const float* __restrict__ aw2, const float* __restrict__ ab2,
    float* __restrict__ yo) {
    __shared__ float smu[NC * PAD];
    __shared__ float smx[NC * PAD];
    __shared__ float ssg[64], sp[64], sh[64];
    __shared__ float red[16];
    int tid = threadIdx.x, w = tid >> 5, lane = tid & 31;
    int bat = blockIdx.x >> 10;
    int tile = blockIdx.x & 1023;
    size_t base = (size_t)bat * CFS + (size_t)tile * TPIX;
    // ---- SE gate, warp-cooperative ----
    if (tid < 64) sp[tid] = g_p[bat * 64 + tid] * (1.f / 65536.f);
    __syncthreads();
    {
        int gq = lane >> 2, t = lane & 3;
        int c = 8 * w + gq;
        const float4* a1 = (const float4*)(aw1 + c * 64 + t * 16);
        float part = 0.f;
#pragma unroll
        for (int q = 0; q < 4; ++q) {
            float4 wv = a1[q];
            int j = t * 16 + q * 4;
            part += wv.x * sp[j] + wv.y * sp[j + 1] + wv.z * sp[j + 2] + wv.w * sp[j + 3];
        }
        part += __shfl_xor_sync(0xffffffffu, part, 1);
        part += __shfl_xor_sync(0xffffffffu, part, 2);
        if (t == 0) sh[c] = fmaxf(part + ab1[c], 0.f);
        __syncthreads();
        const float4* a2 = (const float4*)(aw2 + c * 64 + t * 16);
        part = 0.f;
#pragma unroll
        for (int q = 0; q < 4; ++q) {
            float4 wv = a2[q];
            int j = t * 16 + q * 4;
            part += wv.x * sh[j] + wv.y * sh[j + 1] + wv.z * sh[j + 2] + wv.w * sh[j + 3];
        }
        part += __shfl_xor_sync(0xffffffffu, part, 1);
        part += __shfl_xor_sync(0xffffffffu, part, 2);
        if (t == 0) ssg[c] = sigm(part + ab2[c]);
    }
    __syncthreads();
#pragma unroll
    for (int it = 0; it < 4; ++it) {
        int e = (tid + 256 * it) * 4;
        int row = e >> 6, col = e & 63;
        size_t g = base + (size_t)row * FSZ + col;
        uint2 uv = *(const uint2*)(g_u + g);
        float2 f0 = __half22float2(*(__half2*)&uv.x);
        float2 f1 = __half22float2(*(__half2*)&uv.y);
        float4 xv = *(const float4*)(x + g);
        float sg = ssg[row];
        float4 o;
        o.x = __uint_as_float(f2tf(f0.x * sg));
        o.y = __uint_as_float(f2tf(f0.y * sg));
        o.z = __uint_as_float(f2tf(f1.x * sg));
        o.w = __uint_as_float(f2tf(f1.y * sg));
        *(float4*)(smu + row * PAD + col) = o;
        *(float4*)(smx + row * PAD + col) = xv;
    }
    __syncthreads();
    int mt = w & 3, half = w >> 2;
    int gq = lane >> 2, kc = lane & 3;
    int r0 = mt * 16 + gq, r1r = r0 + 8;
    float acc[4][4];
#pragma unroll
    for (int i = 0; i < 4; ++i)
#pragma unroll
        for (int j = 0; j < 4; ++j) acc[i][j] = 0.f;
#pragma unroll
    for (int kt = 0; kt < 8; ++kt) {
        uint4 A = g_W2f[kt * 256 + tid];
        int kr = kt * 8 + kc;
#pragma unroll
        for (int nt = 0; nt < 4; ++nt) {
            int n0 = half * 32 + nt * 8 + gq;
            unsigned bb0 = __float_as_uint(smu[kr * PAD + n0]);
            unsigned bb1 = __float_as_uint(smu[(kr + 4) * PAD + n0]);
            mma8(acc[nt], A.x, A.y, A.z, A.w, bb0, bb1);
        }
    }
    float bc0 = pb2[r0], bc1 = pb2[r1r];
    float sy = 0.f, syy = 0.f;
    // epilogue in-place on smx (owner-only elements; smx untouched by mma)
#pragma unroll
    for (int nt = 0; nt < 4; ++nt) {
        int c0 = half * 32 + nt * 8 + kc * 2;
        float2 x0 = *(float2*)(smx + r0  * PAD + c0);
        float2 x1 = *(float2*)(smx + r1r * PAD + c0);
        float y00 = acc[nt][0] + bc0 + x0.x;
        float y01 = acc[nt][1] + bc0 + x0.y;
        float y10 = acc[nt][2] + bc1 + x1.x;
        float y11 = acc[nt][3] + bc1 + x1.y;
        *(float2*)(smx + r0  * PAD + c0) = make_float2(y00, y01);
        *(float2*)(smx + r1r * PAD + c0) = make_float2(y10, y11);
        sy  += (y00 + y01) + (y10 + y11);
        syy += (y00 * y00 + y01 * y01) + (y10 * y10 + y11 * y11);
    }
#pragma unroll
    for (int o = 16; o; o >>= 1) {
        sy  += __shfl_xor_sync(0xffffffffu, sy,  o);
        syy += __shfl_xor_sync(0xffffffffu, syy, o);
    }
    if (!lane) { red[w] = sy; red[8 + w] = syy; }
    __syncthreads();
    if (tid == 0) {
        float S = 0.f, SS = 0.f;
#pragma unroll
        for (int i = 0; i < 8; ++i) { S += red[i]; SS += red[8 + i]; }
        atomicAdd(&g_acc[bat * 4 + 2], (double)S);
        atomicAdd(&g_acc[bat * 4 + 3], (double)SS);
    }
#pragma unroll
    for (int it = 0; it < 4; ++it) {
        int e = (tid + 256 * it) * 4;
        int row = e >> 6, col = e & 63;
        *(float4*)(yo + base + (size_t)row * FSZ + col) = *(float4*)(smx + row * PAD + col);
    }
}

// ---------------- K4: LN2 -> GEMM3 -> GLU -> GEMM4 -> +y ----------------
__global__ __launch_bounds__(256, 4) void k_br2(
    const float* __restrict__ lnw, const float* __restrict__ lnb,
    const float* __restrict__ pb3, const float* __restrict__ pb4,
    float* __restrict__ io) {
    __shared__ float smy[NC * PAD];
    __shared__ float smb[NC * PAD];
    __shared__ float st[2];
    int tid = threadIdx.x, w = tid >> 5, lane = tid & 31;
    int bat = blockIdx.x >> 10;
    int tile = blockIdx.x & 1023;
    size_t base  = (size_t)bat * CFS + (size_t)tile * TPIX;
    size_t pbase = (size_t)tile * TPIX;                      // LN params: NO batch dim
    if (tid == 0) {
        double m = g_acc[bat * 4 + 2] * (1.0 / (double)CFS);
        double v = g_acc[bat * 4 + 3] * (1.0 / (double)CFS) - m * m;
        st[0] = (float)m;
        st[1] = (float)(1.0 / sqrt(v + EPSV));
    }
    __syncthreads();
    float m2 = st[0], r2 = st[1];
#pragma unroll
    for (int it = 0; it < 4; ++it) {
        int e = (tid + 256 * it) * 4;
        int row = e >> 6, col = e & 63;
        size_t g  = base  + (size_t)row * FSZ + col;
        size_t gp = pbase + (size_t)row * FSZ + col;
        float4 yv = *(const float4*)(io + g);
        float4 wv = *(const float4*)(lnw + gp);
        float4 bv = *(const float4*)(lnb + gp);
        *(float4*)(smy + row * PAD + col) = yv;
        float4 o;
        o.x = __uint_as_float(f2tf(fmaf((yv.x - m2) * r2, wv.x, bv.x)));
        o.y = __uint_as_float(f2tf(fmaf((yv.y - m2) * r2, wv.y, bv.y)));
        o.z = __uint_as_float(f2tf(fmaf((yv.z - m2) * r2, wv.z, bv.z)));
        o.w = __uint_as_float(f2tf(fmaf((yv.w - m2) * r2, wv.w, bv.w)));
        *(float4*)(smb + row * PAD + col) = o;
    }
    __syncthreads();
    int gq = lane >> 2, kc = lane & 3;
    // GEMM3 (128x64), kt-outer, GLU row pairing
    int ra = 8 * w + gq, rg = ra + 64;
    {
        float acc[8][4];
#pragma unroll
        for (int i = 0; i < 8; ++i)
#pragma unroll
            for (int j = 0; j < 4; ++j) acc[i][j] = 0.f;
#pragma unroll
        for (int kt = 0; kt < 8; ++kt) {
            uint4 A = g_W3f[kt * 256 + tid];
            int kr = kt * 8 + kc;
#pragma unroll
            for (int nt = 0; nt < 8; ++nt) {
                int n0 = nt * 8 + gq;
                unsigned bb0 = __float_as_uint(smb[kr * PAD + n0]);
                unsigned bb1 = __float_as_uint(smb[(kr + 4) * PAD + n0]);
                mma8(acc[nt], A.x, A.y, A.z, A.w, bb0, bb1);
            }
        }
        float b3a = pb3[ra], b3g = pb3[rg];
        __syncthreads();  // done reading ln2 from smb
#pragma unroll
        for (int nt = 0; nt < 8; ++nt) {
            int c0 = nt * 8 + kc * 2;
            float u0 = (acc[nt][0] + b3a) * sigm(acc[nt][2] + b3g);
            float u1 = (acc[nt][1] + b3a) * sigm(acc[nt][3] + b3g);
            float2 uo;
            uo.x = __uint_as_float(f2tf(u0));
            uo.y = __uint_as_float(f2tf(u1));
            *(float2*)(smb + ra * PAD + c0) = uo;
        }
        __syncthreads();
    }
    // GEMM4 (64x64), kt-outer: out = W4@u2 + b4 + y (in-place on smy)
    int mt = w & 3, half = w >> 2;
    int r0 = mt * 16 + gq, r1r = r0 + 8;
    float ac2[4][4];
#pragma unroll
    for (int i = 0; i < 4; ++i)
#pragma unroll
        for (int j = 0; j < 4; ++j) ac2[i][j] = 0.f;
#pragma unroll
    for (int kt = 0; kt < 8; ++kt) {
        uint4 A = g_W4f[kt * 256 + tid];
        int kr = kt * 8 + kc;
#pragma unroll
        for (int nt = 0; nt < 4; ++nt) {
            int n0 = half * 32 + nt * 8 + gq;
            unsigned bb0 = __float_as_uint(smb[kr * PAD + n0]);
            unsigned bb1 = __float_as_uint(smb[(kr + 4) * PAD + n0]);
            mma8(ac2[nt], A.x, A.y, A.z, A.w, bb0, bb1);
        }
    }
    float b40 = pb4[r0], b41 = pb4[r1r];
#pragma unroll
    for (int nt = 0; nt < 4; ++nt) {
        int c0 = half * 32 + nt * 8 + kc * 2;
        float2 y0 = *(float2*)(smy + r0  * PAD + c0);
        float2 y1 = *(float2*)(smy + r1r * PAD + c0);
        *(float2*)(smy + r0  * PAD + c0) = make_float2(ac2[nt][0] + b40 + y0.x,
                                                       ac2[nt][1] + b40 + y0.y);
        *(float2*)(smy + r1r * PAD + c0) = make_float2(ac2[nt][2] + b41 + y1.x,
                                                       ac2[nt][3] + b41 + y1.y);
    }
    __syncthreads();
#pragma unroll
    for (int it = 0; it < 4; ++it) {
        int e = (tid + 256 * it) * 4;
        int row = e >> 6, col = e & 63;
        *(float4*)(io + base + (size_t)row * FSZ + col) = *(float4*)(smy + row * PAD + col);
    }
}

// ---------------- launch ----------------
extern "C" void kernel_launch(void* const* d_in, const int* in_sizes, int n_in,
                              void* d_out, int out_size) {
    const float* x   = (const float*)d_in[0];
    const float* l1w = (const float*)d_in[1];
    const float* l1b = (const float*)d_in[2];
    const float* l2w = (const float*)d_in[3];
    const float* l2b = (const float*)d_in[4];
    const float* W1  = (const float*)d_in[5];
    const float* b1  = (const float*)d_in[6];
    const float* dww = (const float*)d_in[7];
    const float* dwb = (const float*)d_in[8];
    const float* aw1 = (const float*)d_in[9];
    const float* ab1 = (const float*)d_in[10];
    const float* aw2 = (const float*)d_in[11];
    const float* ab2 = (const float*)d_in[12];
    const float* W2  = (const float*)d_in[13];
    const float* b2  = (const float*)d_in[14];
    const float* W3  = (const float*)d_in[15];
    const float* b3  = (const float*)d_in[16];
    const float* W4  = (const float*)d_in[17];
    const float* b4  = (const float*)d_in[18];
    float* out = (float*)d_out;

    k_init  <<<5, 256>>>(W1, W2, W3, W4);
    k_stats1<<<NB * 512, 256>>>(x);
    k_br1   <<<NB * 1024, 256>>>(x, l1w, l1b, b1, dww, dwb);
    k_y     <<<NB * 1024, 256>>>(x, b2, aw1, ab1, aw2, ab2, out);
    k_br2   <<<NB * 1024, 256>>>(l2w, l2b, b3, b4, out);
}